// round 15
// baseline (speedup 1.0000x reference)
#include <cuda_runtime.h>
#include <cuda_bf16.h>
#include <math.h>
#include <stdint.h>

#define Nn 4
#define Cc 512
#define Ll 4096
#define Dd 256
#define Kk 8192
#define Pp (Nn*Ll)
#define OUT_Y ((size_t)Nn*Cc*Ll)
#define OUT_LOSS (OUT_Y + Pp)

typedef unsigned long long u64;
typedef unsigned int u32;

// ---- packed fp32x2 FMA (scalar GEMMs) ----
#define FMA2(d, a, b, c) asm("fma.rn.f32x2 %0, %1, %2, %3;" : "=l"(d) : "l"(a), "l"(b), "l"(c))
#define DUP2(d, s)       asm("mov.b64 %0, {%1, %1};" : "=l"(d) : "f"(s))
__device__ __forceinline__ float lo32f(u64 v){ return __uint_as_float((unsigned)(v & 0xffffffffu)); }
__device__ __forceinline__ float hi32f(u64 v){ return __uint_as_float((unsigned)(v >> 32)); }

// ---- mma.sync + cp.async (baseline sm_80+ PTX, OK for plain sm_103) ----
#define MMA_AB(d, A, B) \
    asm volatile("mma.sync.aligned.m16n8k16.row.col.f32.bf16.bf16.f32 " \
        "{%0,%1,%2,%3}, {%4,%5,%6,%7}, {%8,%9}, {%0,%1,%2,%3};" \
        : "+f"((d)[0]), "+f"((d)[1]), "+f"((d)[2]), "+f"((d)[3]) \
        : "r"((A).x), "r"((A).y), "r"((A).z), "r"((A).w), "r"((B).x), "r"((B).y))
#define MMA_Z(d, A, B) \
    asm volatile("mma.sync.aligned.m16n8k16.row.col.f32.bf16.bf16.f32 " \
        "{%0,%1,%2,%3}, {%4,%5,%6,%7}, {%8,%9}, {%10,%10,%10,%10};" \
        : "=f"((d)[0]), "=f"((d)[1]), "=f"((d)[2]), "=f"((d)[3]) \
        : "r"((A).x), "r"((A).y), "r"((A).z), "r"((A).w), "r"((B).x), "r"((B).y), "f"(0.0f))
#define CPA16(s, g) asm volatile("cp.async.cg.shared.global [%0], [%1], 16;" :: "r"(s), "l"(g) : "memory")
#define CPC()       asm volatile("cp.async.commit_group;" ::: "memory")
#define CPW(n)      asm volatile("cp.async.wait_group %0;" :: "n"(n) : "memory")

__device__ __forceinline__ uint32_t smem_u32(const void* p){
    uint32_t a; asm("{ .reg .u64 t; cvta.to.shared.u64 t, %1; cvt.u32.u64 %0, t; }" : "=r"(a) : "l"(p)); return a;
}
__device__ __forceinline__ u32 mono_enc(float f){
    u32 u = __float_as_uint(f);
    return (u & 0x80000000u) ? ~u : (u | 0x80000000u);
}
__device__ __forceinline__ float mono_dec(u32 e){
    return __uint_as_float((e & 0x80000000u) ? (e & 0x7FFFFFFFu) : ~e);
}

// -------- device scratch --------
__device__ float g_Win[Dd*Cc];
__device__ float g_Wout[Cc*Dd];
__device__ float g_Wq[(size_t)Kk*Cc];
__device__ float g_invn[Kk];
__device__ float g_zet[(size_t)Pp*Dd];
__device__ float g_anorm[Pp];
__device__ int   g_idx[Pp];
__device__ float g_losspart[Pp/64];
// fragment-ready bf16 operands (u32 = 2 bf16)
__device__ u32 g_Afr[(size_t)(Pp/16)*16*32*4];     // [rblk][t][lane][reg]
__device__ u32 g_Bfr[(size_t)(Kk/128)*16*16*32*2]; // [grp][t][j][lane][reg]

#define MICRO_FMA2(acc2, aA, aB, b4) do { \
        u64 bb0, bb1, bb2, bb3; \
        DUP2(bb0, (b4).x); DUP2(bb1, (b4).y); DUP2(bb2, (b4).z); DUP2(bb3, (b4).w); \
        FMA2(acc2[0][0], (aA).x, bb0, acc2[0][0]); FMA2(acc2[0][1], (aA).x, bb1, acc2[0][1]); \
        FMA2(acc2[0][2], (aA).x, bb2, acc2[0][2]); FMA2(acc2[0][3], (aA).x, bb3, acc2[0][3]); \
        FMA2(acc2[1][0], (aA).y, bb0, acc2[1][0]); FMA2(acc2[1][1], (aA).y, bb1, acc2[1][1]); \
        FMA2(acc2[1][2], (aA).y, bb2, acc2[1][2]); FMA2(acc2[1][3], (aA).y, bb3, acc2[1][3]); \
        FMA2(acc2[2][0], (aB).x, bb0, acc2[2][0]); FMA2(acc2[2][1], (aB).x, bb1, acc2[2][1]); \
        FMA2(acc2[2][2], (aB).x, bb2, acc2[2][2]); FMA2(acc2[2][3], (aB).x, bb3, acc2[2][3]); \
        FMA2(acc2[3][0], (aB).y, bb0, acc2[3][0]); FMA2(acc2[3][1], (aB).y, bb1, acc2[3][1]); \
        FMA2(acc2[3][2], (aB).y, bb2, acc2[3][2]); FMA2(acc2[3][3], (aB).y, bb3, acc2[3][3]); \
    } while (0)

// ================= prep =================
__global__ void __launch_bounds__(128) prep_wn_kernel(
    const float* __restrict__ v, const float* __restrict__ g, int cols, int sel)
{
    float* W = sel ? g_Wout : g_Win;
    const int r = blockIdx.x, tid = threadIdx.x;
    float s = 0.f;
    for (int c = tid; c < cols; c += 128) { float t = v[(size_t)r*cols + c]; s = fmaf(t, t, s); }
    #pragma unroll
    for (int m = 16; m; m >>= 1) s += __shfl_xor_sync(0xffffffffu, s, m);
    __shared__ float red[4];
    if ((tid & 31) == 0) red[tid >> 5] = s;
    __syncthreads();
    s = red[0] + red[1] + red[2] + red[3];
    const float scale = g[r] / sqrtf(s);
    for (int c = tid; c < cols; c += 128)
        W[(size_t)r*cols + c] = v[(size_t)r*cols + c] * scale;
}

__global__ void __launch_bounds__(128) prep_cbinv_kernel(const float* __restrict__ cb)
{
    const int r = blockIdx.x, tid = threadIdx.x;
    float s = 0.f;
    for (int c = tid; c < Dd; c += 128) { float t = cb[(size_t)r*Dd + c]; s = fmaf(t, t, s); }
    #pragma unroll
    for (int m = 16; m; m >>= 1) s += __shfl_xor_sync(0xffffffffu, s, m);
    __shared__ float red[4];
    if ((tid & 31) == 0) red[tid >> 5] = s;
    __syncthreads();
    if (tid == 0) {
        s = red[0] + red[1] + red[2] + red[3];
        g_invn[r] = 1.f / fmaxf(sqrtf(s), 1e-8f);
    }
}

// ================= z_e GEMM (fp32, exact) =================
__global__ void __launch_bounds__(128) ze_gemm_kernel(
    const float* __restrict__ x, const float* __restrict__ inb)
{
    __shared__ float xs[32][64];
    __shared__ float ws[32][68];
    const int tid = threadIdx.x, ty = tid >> 4, tx = tid & 15;
    const int l0 = blockIdx.x * 64, d0 = blockIdx.y * 64, n = blockIdx.z;
    const float* xn = x + (size_t)n * Cc * Ll;
    u64 acc2[4][4];
    #pragma unroll
    for (int i = 0; i < 4; i++) { acc2[i][0]=0; acc2[i][1]=0; acc2[i][2]=0; acc2[i][3]=0; }
    for (int c0 = 0; c0 < Cc; c0 += 32) {
        for (int i = tid; i < 32*64; i += 128) { int c = i >> 6, l = i & 63; xs[c][l] = xn[(size_t)(c0 + c)*Ll + l0 + l]; }
        for (int i = tid; i < 64*32; i += 128) { int d = i >> 5, c = i & 31; ws[c][d] = g_Win[(d0 + d)*Cc + c0 + c]; }
        __syncthreads();
        #pragma unroll 8
        for (int c = 0; c < 32; c++) {
            ulonglong2 aA = *(const ulonglong2*)&xs[c][ty*8];
            ulonglong2 aB = *(const ulonglong2*)&xs[c][ty*8 + 4];
            float4 b = *(const float4*)&ws[c][tx*4];
            MICRO_FMA2(acc2, aA, aB, b);
        }
        __syncthreads();
    }
    const float b0 = inb[d0+tx*4], b1 = inb[d0+tx*4+1], b2 = inb[d0+tx*4+2], b3 = inb[d0+tx*4+3];
    #pragma unroll
    for (int i2 = 0; i2 < 4; i2++)
        #pragma unroll
        for (int h = 0; h < 2; h++) {
            int l = l0 + ty*8 + i2*2 + h;
            float4 o;
            o.x = (h ? hi32f(acc2[i2][0]) : lo32f(acc2[i2][0])) + b0;
            o.y = (h ? hi32f(acc2[i2][1]) : lo32f(acc2[i2][1])) + b1;
            o.z = (h ? hi32f(acc2[i2][2]) : lo32f(acc2[i2][2])) + b2;
            o.w = (h ? hi32f(acc2[i2][3]) : lo32f(acc2[i2][3])) + b3;
            *(float4*)&g_zet[((size_t)(n*Ll + l))*Dd + d0 + tx*4] = o;
        }
}

// ================= Wq GEMM =================
__global__ void __launch_bounds__(128) wq_gemm_kernel(const float* __restrict__ cb)
{
    __shared__ float as_[32][68];
    __shared__ float bs_[32][68];
    const int tid = threadIdx.x, ty = tid >> 4, tx = tid & 15;
    const int k0 = blockIdx.x * 64, c0 = blockIdx.y * 64;
    u64 acc2[4][4];
    #pragma unroll
    for (int i = 0; i < 4; i++) { acc2[i][0]=0; acc2[i][1]=0; acc2[i][2]=0; acc2[i][3]=0; }
    for (int d0 = 0; d0 < Dd; d0 += 32) {
        for (int i = tid; i < 64*32; i += 128) { int k = i >> 5, d = i & 31; as_[d][k] = cb[(size_t)(k0 + k)*Dd + d0 + d]; }
        for (int i = tid; i < 64*32; i += 128) { int c = i >> 5, d = i & 31; bs_[d][c] = g_Wout[(c0 + c)*Dd + d0 + d]; }
        __syncthreads();
        #pragma unroll 8
        for (int d = 0; d < 32; d++) {
            ulonglong2 aA = *(const ulonglong2*)&as_[d][ty*8];
            ulonglong2 aB = *(const ulonglong2*)&as_[d][ty*8 + 4];
            float4 b = *(const float4*)&bs_[d][tx*4];
            MICRO_FMA2(acc2, aA, aB, b);
        }
        __syncthreads();
    }
    #pragma unroll
    for (int i2 = 0; i2 < 4; i2++)
        #pragma unroll
        for (int h = 0; h < 2; h++) {
            int k = k0 + ty*8 + i2*2 + h;
            float4 o;
            o.x = h ? hi32f(acc2[i2][0]) : lo32f(acc2[i2][0]);
            o.y = h ? hi32f(acc2[i2][1]) : lo32f(acc2[i2][1]);
            o.z = h ? hi32f(acc2[i2][2]) : lo32f(acc2[i2][2]);
            o.w = h ? hi32f(acc2[i2][3]) : lo32f(acc2[i2][3]);
            *(float4*)&g_Wq[(size_t)k*Cc + c0 + tx*4] = o;
        }
}

// ================= anorm =================
__global__ void __launch_bounds__(256) anorm_kernel()
{
    const int w = threadIdx.x >> 5, lane = threadIdx.x & 31;
    const int pos = blockIdx.x * 8 + w;
    const float4* r = (const float4*)(g_zet + (size_t)pos*Dd);
    float4 a = r[lane*2], b = r[lane*2 + 1];
    float s = a.x*a.x + a.y*a.y + a.z*a.z + a.w*a.w + b.x*b.x + b.y*b.y + b.z*b.z + b.w*b.w;
    #pragma unroll
    for (int m = 16; m; m >>= 1) s += __shfl_xor_sync(0xffffffffu, s, m);
    if (lane == 0) g_anorm[pos] = sqrtf(s);
}

// ================= fragment-layout bf16 conversions =================
__global__ void __launch_bounds__(256) split_ze_kernel()
{
    const size_t i = (size_t)blockIdx.x * 256 + threadIdx.x;
    const int pos = (int)(i >> 8), d = (int)(i & 255);
    const int r = pos >> 4, row = pos & 15, t = d >> 4, kk = d & 15;
    const int lane = (row & 7)*4 + ((kk & 7) >> 1);
    const int reg = ((kk >> 3) << 1) | (row >> 3);
    const size_t u32i = (((size_t)r*16 + t)*32 + lane)*4 + reg;
    ((__nv_bfloat16*)g_Afr)[u32i*2 + (kk & 1)] = __float2bfloat16(g_zet[i]);
}
__global__ void __launch_bounds__(256) split_cb_kernel(const float* __restrict__ cb)
{
    const size_t i = (size_t)blockIdx.x * 256 + threadIdx.x;
    const int k = (int)(i >> 8), d = (int)(i & 255);
    const int g = k >> 7, rowc = k & 127, j = rowc >> 3, n = rowc & 7;
    const int t = d >> 4, kk = d & 15;
    const int lane = n*4 + ((kk & 7) >> 1);
    const int reg = kk >> 3;
    const size_t u32i = (size_t)g*16384 + (((size_t)t*16 + j)*32 + lane)*2 + reg;
    ((__nv_bfloat16*)g_Bfr)[u32i*2 + (kk & 1)] = __float2bfloat16(cb[i] * g_invn[k]);
}

// ================= single-GEMM screen + deferred group rescore =================
// CTA = 128 positions, 256 threads (8 warps: 4 pos-rowgroups x 2 code-colgroups).
// GEMM loop records only a per-(pos, 128-code-group) bf16-sim max (cheap
// fire-and-forget smem atomicMax). After the loop: tf = maxbf - margin; warps
// rescore all codes of flagged groups in exact fp32. Superset proof: the true
// argmax's group has groupmax >= maxbf - 2m >= tf; any non-rescored code has
// sim_fp < maxbf - m <= max_fp, so it can neither win nor tie.
__global__ void __launch_bounds__(256, 1) mma_search_kernel(
    const float* __restrict__ cb, float* __restrict__ out)
{
    extern __shared__ unsigned char dsm[];   // [0,64K): A  [64K,96K): B0  [96K,128K): B1
    __shared__ u32 gmax[128*64];             // 32KB mono-encoded per (pos, group)
    __shared__ u64 sb64[128];
    __shared__ float tfs[128];

    const int tid = threadIdx.x, w = tid >> 5, lane = tid & 31;
    const int rowgrp = w & 3, colgrp = w >> 2;
    const int p0 = blockIdx.x * 128;
    const uint32_t sbase = smem_u32(dsm);
    const uint4* sAv = (const uint4*)dsm;

    if (tid < 128) sb64[tid] = 0ull;
    for (int i = tid; i < 128*64; i += 256) gmax[i] = 0u;

    // prime: A tile (64KB) + B tile 0 (32KB = 64 codes)
    {
        const char* Asrc = (const char*)g_Afr + (size_t)(p0 >> 4) * 8192;
        for (int it = 0; it < 16; it++) {
            int off = (it*256 + tid) * 16;
            CPA16(sbase + off, Asrc + off);
        }
        for (int it = 0; it < 8; it++) {
            int u = it*256 + tid;                 // 16B unit in tile
            int t = u >> 7, within = u & 127;
            const u32* src = g_Bfr + (size_t)t*1024 + within*4;   // g=0, hh=0
            CPA16(sbase + 65536 + u*16, (const char*)src);
        }
        CPC();
    }

    int pps[4];
    #pragma unroll
    for (int mt = 0; mt < 2; mt++)
        #pragma unroll
        for (int eh = 0; eh < 2; eh++)
            pps[mt*2 + eh] = rowgrp*32 + mt*16 + (lane >> 2) + eh*8;

    for (int tt = 0; tt < 128; tt++) {        // 64-code tiles
        __syncthreads();   // prior compute done before overwriting the other buf
        if (tt < 127) {
            const int nt = tt + 1, ng = nt >> 1, nh = nt & 1;
            uint32_t dst = sbase + 65536 + (nt & 1) * 32768;
            for (int it = 0; it < 8; it++) {
                int u = it*256 + tid;
                int t = u >> 7, within = u & 127;
                const u32* src = g_Bfr + (size_t)ng*16384 + (size_t)t*1024 + nh*512 + within*4;
                CPA16(dst + u*16, (const char*)src);
            }
            CPC();
            CPW(1);
        } else {
            CPW(0);
        }
        __syncthreads();

        const uint2* sBv = (const uint2*)(dsm + 65536 + (size_t)(tt & 1) * 32768);
        float d0[4][4], d1[4][4];
        #pragma unroll
        for (int t = 0; t < 16; t++) {
            uint4 A0 = sAv[(rowgrp*32 + t)*32 + lane];
            uint4 A1 = sAv[(rowgrp*32 + 16 + t)*32 + lane];
            #pragma unroll
            for (int j = 0; j < 4; j++) {
                uint2 B = sBv[(t*8 + colgrp*4 + j)*32 + lane];
                if (t == 0) { MMA_Z(d0[j], A0, B); MMA_Z(d1[j], A1, B); }
                else        { MMA_AB(d0[j], A0, B); MMA_AB(d1[j], A1, B); }
            }
        }

        // minimal epilogue: per-slot max -> quad reduce -> smem atomicMax
        const int grp = tt >> 1;
        #pragma unroll
        for (int mt = 0; mt < 2; mt++) {
            float (*dd)[4] = mt ? d1 : d0;
            #pragma unroll
            for (int eh = 0; eh < 2; eh++) {
                float m = fmaxf(dd[0][eh*2], dd[0][eh*2 + 1]);
                #pragma unroll
                for (int j = 1; j < 4; j++)
                    m = fmaxf(m, fmaxf(dd[j][eh*2], dd[j][eh*2 + 1]));
                float mq = fmaxf(m, __shfl_xor_sync(0xffffffffu, m, 1));
                mq = fmaxf(mq, __shfl_xor_sync(0xffffffffu, mq, 2));
                if ((lane & 3) == 0)
                    atomicMax(&gmax[pps[mt*2 + eh]*64 + grp], mono_enc(mq));
            }
        }
    }

    __syncthreads();
    // per-position threshold from group maxima
    if (tid < 128) {
        u32 mx = 0u;
        #pragma unroll 8
        for (int g = 0; g < 64; g++) mx = max(mx, gmax[tid*64 + g]);
        tfs[tid] = mono_dec(mx) - 0.012f * g_anorm[p0 + tid];
    }
    __syncthreads();

    // deferred rescore: warp w owns positions w*16 .. w*16+15
    for (int pi = 0; pi < 16; pi++) {
        const int pos = w*16 + pi;
        const float tf = tfs[pos];
        #pragma unroll
        for (int half = 0; half < 2; half++) {
            const int g = half*32 + lane;
            const bool hit = mono_dec(gmax[pos*64 + g]) >= tf;
            u32 bal = __ballot_sync(0xffffffffu, hit);
            while (bal) {
                const int gg = __ffs(bal) - 1; bal &= bal - 1;
                const int kb = (half*32 + gg)*128 + lane*4;   // 4 codes per lane
                // exact fp32 dots for 4 codes
                const float4* ar = (const float4*)(g_zet + (size_t)(p0 + pos)*Dd);
                const float4* b0r = (const float4*)(cb + (size_t)(kb + 0)*Dd);
                const float4* b1r = (const float4*)(cb + (size_t)(kb + 1)*Dd);
                const float4* b2r = (const float4*)(cb + (size_t)(kb + 2)*Dd);
                const float4* b3r = (const float4*)(cb + (size_t)(kb + 3)*Dd);
                float s0 = 0.f, s1 = 0.f, s2 = 0.f, s3 = 0.f;
                #pragma unroll 8
                for (int i = 0; i < 64; i++) {
                    float4 a = ar[i];
                    float4 b0 = b0r[i], b1 = b1r[i], b2 = b2r[i], b3 = b3r[i];
                    s0 = fmaf(a.x, b0.x, s0); s0 = fmaf(a.y, b0.y, s0); s0 = fmaf(a.z, b0.z, s0); s0 = fmaf(a.w, b0.w, s0);
                    s1 = fmaf(a.x, b1.x, s1); s1 = fmaf(a.y, b1.y, s1); s1 = fmaf(a.z, b1.z, s1); s1 = fmaf(a.w, b1.w, s1);
                    s2 = fmaf(a.x, b2.x, s2); s2 = fmaf(a.y, b2.y, s2); s2 = fmaf(a.z, b2.z, s2); s2 = fmaf(a.w, b2.w, s2);
                    s3 = fmaf(a.x, b3.x, s3); s3 = fmaf(a.y, b3.y, s3); s3 = fmaf(a.z, b3.z, s3); s3 = fmaf(a.w, b3.w, s3);
                }
                // pack (value, 8191-k); lane-local best over 4 codes, then warp-reduce
                u64 best = ((u64)mono_enc(s0 * __ldg(&g_invn[kb + 0])) << 32) | (u64)(u32)(8191 - (kb + 0));
                u64 c1   = ((u64)mono_enc(s1 * __ldg(&g_invn[kb + 1])) << 32) | (u64)(u32)(8191 - (kb + 1));
                u64 c2   = ((u64)mono_enc(s2 * __ldg(&g_invn[kb + 2])) << 32) | (u64)(u32)(8191 - (kb + 2));
                u64 c3   = ((u64)mono_enc(s3 * __ldg(&g_invn[kb + 3])) << 32) | (u64)(u32)(8191 - (kb + 3));
                if (c1 > best) best = c1;
                if (c2 > best) best = c2;
                if (c3 > best) best = c3;
                #pragma unroll
                for (int m = 16; m; m >>= 1) {
                    u64 o = __shfl_xor_sync(0xffffffffu, best, m);
                    if (o > best) best = o;
                }
                if (lane == 0) atomicMax(&sb64[pos], best);
            }
        }
    }

    __syncthreads();
    if (tid < 128) {
        int k = 8191 - (int)(u32)(sb64[tid] & 0xFFFFFFFFull);
        g_idx[p0 + tid] = k;
        out[OUT_Y + p0 + tid] = (float)k;
    }
}

// ================= VQ loss =================
__global__ void __launch_bounds__(128) loss_kernel(const float* __restrict__ cb)
{
    __shared__ float lred[4];
    const int tid = threadIdx.x;
    const int p0 = blockIdx.x * 64;
    float ls = 0.f;
    for (int i = tid; i < 64*256; i += 128) {
        int pos = i >> 8, d = i & 255;
        int ix = g_idx[p0 + pos];
        float diff = cb[(size_t)ix*Dd + d] - g_zet[(size_t)(p0 + pos)*Dd + d];
        ls = fmaf(diff, diff, ls);
    }
    #pragma unroll
    for (int m = 16; m; m >>= 1) ls += __shfl_xor_sync(0xffffffffu, ls, m);
    if ((tid & 31) == 0) lred[tid >> 5] = ls;
    __syncthreads();
    if (tid == 0) g_losspart[blockIdx.x] = lred[0] + lred[1] + lred[2] + lred[3];
}

// ================= y gather =================
__global__ void __launch_bounds__(256) gather_kernel(
    const float* __restrict__ outb, float* __restrict__ out)
{
    extern __shared__ float sm[];
    __shared__ int sidx[32];
    const int tid = threadIdx.x;
    const int l0 = blockIdx.x * 32, n = blockIdx.y;
    if (tid < 32) sidx[tid] = g_idx[n*Ll + l0 + tid];
    __syncthreads();
    for (int i = tid; i < 32*512; i += 256) {
        int l = i >> 9, c = i & 511;
        sm[l*513 + c] = g_Wq[(size_t)sidx[l]*Cc + c];
    }
    __syncthreads();
    for (int i = tid; i < 512*32; i += 256) {
        int c = i >> 5, l = i & 31;
        out[((size_t)n*Cc + c)*Ll + l0 + l] = sm[l*513 + c] + __ldg(&outb[c]);
    }
}

// ================= finalize losses =================
__global__ void finalize_kernel(float* __restrict__ out)
{
    const int tid = threadIdx.x;
    const int n = tid >> 5, lane = tid & 31;
    float s = g_losspart[n*64 + lane] + g_losspart[n*64 + 32 + lane];
    #pragma unroll
    for (int m = 16; m; m >>= 1) s += __shfl_xor_sync(0xffffffffu, s, m);
    if (lane == 0) {
        float v = s * (1.0f / (float)(Dd * Ll));
        out[OUT_LOSS + n]     = v;
        out[OUT_LOSS + 4 + n] = v;
    }
}

// ================= launch =================
extern "C" void kernel_launch(void* const* d_in, const int* in_sizes, int n_in,
                              void* d_out, int out_size)
{
    (void)in_sizes; (void)n_in; (void)out_size;
    const float* x    = (const float*)d_in[0];
    const float* vin  = (const float*)d_in[1];
    const float* gin  = (const float*)d_in[2];
    const float* bin  = (const float*)d_in[3];
    const float* vout = (const float*)d_in[4];
    const float* gout = (const float*)d_in[5];
    const float* bout = (const float*)d_in[6];
    const float* cb   = (const float*)d_in[7];
    float* out = (float*)d_out;

    const int MMA_SMEM    = 131072;      // 64KB A + 2x32KB B
    const int GATHER_SMEM = 32*513*4;
    cudaFuncSetAttribute(mma_search_kernel, cudaFuncAttributeMaxDynamicSharedMemorySize, MMA_SMEM);
    cudaFuncSetAttribute(mma_search_kernel, cudaFuncAttributePreferredSharedMemoryCarveout, 100);
    cudaFuncSetAttribute(gather_kernel, cudaFuncAttributeMaxDynamicSharedMemorySize, GATHER_SMEM);

    prep_wn_kernel<<<Dd, 128>>>(vin, gin, Cc, 0);
    prep_wn_kernel<<<Cc, 128>>>(vout, gout, Dd, 1);
    prep_cbinv_kernel<<<Kk, 128>>>(cb);
    ze_gemm_kernel<<<dim3(Ll/64, Dd/64, Nn), 128>>>(x, bin);
    anorm_kernel<<<Pp/8, 256>>>();
    split_ze_kernel<<<(int)(((size_t)Pp*Dd)/256), 256>>>();
    split_cb_kernel<<<(int)(((size_t)Kk*Dd)/256), 256>>>(cb);
    wq_gemm_kernel<<<dim3(Kk/64, Cc/64), 128>>>(cb);
    mma_search_kernel<<<Pp/128, 256, MMA_SMEM>>>(cb, out);
    loss_kernel<<<Pp/64, 128>>>(cb);
    gather_kernel<<<dim3(Ll/32, Nn), 256, GATHER_SMEM>>>(bout, out);
    finalize_kernel<<<1, 128>>>(out);
}

// round 16
// speedup vs baseline: 4.1743x; 4.1743x over previous
#include <cuda_runtime.h>
#include <cuda_bf16.h>
#include <math.h>
#include <stdint.h>

#define Nn 4
#define Cc 512
#define Ll 4096
#define Dd 256
#define Kk 8192
#define Pp (Nn*Ll)
#define OUT_Y ((size_t)Nn*Cc*Ll)
#define OUT_LOSS (OUT_Y + Pp)
#define QCAP (1u<<20)

typedef unsigned long long u64;
typedef unsigned int u32;

// ---- packed fp32x2 FMA (scalar GEMMs) ----
#define FMA2(d, a, b, c) asm("fma.rn.f32x2 %0, %1, %2, %3;" : "=l"(d) : "l"(a), "l"(b), "l"(c))
#define DUP2(d, s)       asm("mov.b64 %0, {%1, %1};" : "=l"(d) : "f"(s))
__device__ __forceinline__ float lo32f(u64 v){ return __uint_as_float((unsigned)(v & 0xffffffffu)); }
__device__ __forceinline__ float hi32f(u64 v){ return __uint_as_float((unsigned)(v >> 32)); }

// ---- mma.sync + cp.async (baseline sm_80+ PTX, OK for plain sm_103) ----
#define MMA_AB(d, A, B) \
    asm volatile("mma.sync.aligned.m16n8k16.row.col.f32.bf16.bf16.f32 " \
        "{%0,%1,%2,%3}, {%4,%5,%6,%7}, {%8,%9}, {%0,%1,%2,%3};" \
        : "+f"((d)[0]), "+f"((d)[1]), "+f"((d)[2]), "+f"((d)[3]) \
        : "r"((A).x), "r"((A).y), "r"((A).z), "r"((A).w), "r"((B).x), "r"((B).y))
#define MMA_Z(d, A, B) \
    asm volatile("mma.sync.aligned.m16n8k16.row.col.f32.bf16.bf16.f32 " \
        "{%0,%1,%2,%3}, {%4,%5,%6,%7}, {%8,%9}, {%10,%10,%10,%10};" \
        : "=f"((d)[0]), "=f"((d)[1]), "=f"((d)[2]), "=f"((d)[3]) \
        : "r"((A).x), "r"((A).y), "r"((A).z), "r"((A).w), "r"((B).x), "r"((B).y), "f"(0.0f))
#define CPA16(s, g) asm volatile("cp.async.cg.shared.global [%0], [%1], 16;" :: "r"(s), "l"(g) : "memory")
#define CPC()       asm volatile("cp.async.commit_group;" ::: "memory")
#define CPW(n)      asm volatile("cp.async.wait_group %0;" :: "n"(n) : "memory")

__device__ __forceinline__ uint32_t smem_u32(const void* p){
    uint32_t a; asm("{ .reg .u64 t; cvta.to.shared.u64 t, %1; cvt.u32.u64 %0, t; }" : "=r"(a) : "l"(p)); return a;
}
__device__ __forceinline__ u32 mono_enc(float f){
    u32 u = __float_as_uint(f);
    return (u & 0x80000000u) ? ~u : (u | 0x80000000u);
}
__device__ __forceinline__ float mono_dec(u32 e){
    return __uint_as_float((e & 0x80000000u) ? (e & 0x7FFFFFFFu) : ~e);
}

// -------- device scratch --------
__device__ float g_Win[Dd*Cc];
__device__ float g_Wout[Cc*Dd];
__device__ float g_Wq[(size_t)Kk*Cc];
__device__ float g_invn[Kk];
__device__ float g_zet[(size_t)Pp*Dd];
__device__ float g_anorm[Pp];
__device__ int   g_idx[Pp];
__device__ float g_losspart[Pp/64];
__device__ u32   g_qcnt;
__device__ u32   g_queue[QCAP];          // packed: pos<<13 | k
__device__ u64   g_sb64[Pp];             // packed (mono value, 8191-k)
// fragment-ready bf16 operands (u32 = 2 bf16)
__device__ u32 g_Afr[(size_t)(Pp/16)*16*32*4];     // [rblk][t][lane][reg]
__device__ u32 g_Bfr[(size_t)(Kk/128)*16*16*32*2]; // [grp][t][j][lane][reg]

#define MICRO_FMA2(acc2, aA, aB, b4) do { \
        u64 bb0, bb1, bb2, bb3; \
        DUP2(bb0, (b4).x); DUP2(bb1, (b4).y); DUP2(bb2, (b4).z); DUP2(bb3, (b4).w); \
        FMA2(acc2[0][0], (aA).x, bb0, acc2[0][0]); FMA2(acc2[0][1], (aA).x, bb1, acc2[0][1]); \
        FMA2(acc2[0][2], (aA).x, bb2, acc2[0][2]); FMA2(acc2[0][3], (aA).x, bb3, acc2[0][3]); \
        FMA2(acc2[1][0], (aA).y, bb0, acc2[1][0]); FMA2(acc2[1][1], (aA).y, bb1, acc2[1][1]); \
        FMA2(acc2[1][2], (aA).y, bb2, acc2[1][2]); FMA2(acc2[1][3], (aA).y, bb3, acc2[1][3]); \
        FMA2(acc2[2][0], (aB).x, bb0, acc2[2][0]); FMA2(acc2[2][1], (aB).x, bb1, acc2[2][1]); \
        FMA2(acc2[2][2], (aB).x, bb2, acc2[2][2]); FMA2(acc2[2][3], (aB).x, bb3, acc2[2][3]); \
        FMA2(acc2[3][0], (aB).y, bb0, acc2[3][0]); FMA2(acc2[3][1], (aB).y, bb1, acc2[3][1]); \
        FMA2(acc2[3][2], (aB).y, bb2, acc2[3][2]); FMA2(acc2[3][3], (aB).y, bb3, acc2[3][3]); \
    } while (0)

// ================= prep =================
__global__ void __launch_bounds__(128) prep_wn_kernel(
    const float* __restrict__ v, const float* __restrict__ g, int cols, int sel)
{
    float* W = sel ? g_Wout : g_Win;
    const int r = blockIdx.x, tid = threadIdx.x;
    float s = 0.f;
    for (int c = tid; c < cols; c += 128) { float t = v[(size_t)r*cols + c]; s = fmaf(t, t, s); }
    #pragma unroll
    for (int m = 16; m; m >>= 1) s += __shfl_xor_sync(0xffffffffu, s, m);
    __shared__ float red[4];
    if ((tid & 31) == 0) red[tid >> 5] = s;
    __syncthreads();
    s = red[0] + red[1] + red[2] + red[3];
    const float scale = g[r] / sqrtf(s);
    for (int c = tid; c < cols; c += 128)
        W[(size_t)r*cols + c] = v[(size_t)r*cols + c] * scale;
}

__global__ void __launch_bounds__(128) prep_cbinv_kernel(const float* __restrict__ cb)
{
    const int r = blockIdx.x, tid = threadIdx.x;
    float s = 0.f;
    for (int c = tid; c < Dd; c += 128) { float t = cb[(size_t)r*Dd + c]; s = fmaf(t, t, s); }
    #pragma unroll
    for (int m = 16; m; m >>= 1) s += __shfl_xor_sync(0xffffffffu, s, m);
    __shared__ float red[4];
    if ((tid & 31) == 0) red[tid >> 5] = s;
    __syncthreads();
    if (tid == 0) {
        s = red[0] + red[1] + red[2] + red[3];
        g_invn[r] = 1.f / fmaxf(sqrtf(s), 1e-8f);
    }
}

// ================= z_e GEMM (fp32, exact) =================
__global__ void __launch_bounds__(128) ze_gemm_kernel(
    const float* __restrict__ x, const float* __restrict__ inb)
{
    __shared__ float xs[32][64];
    __shared__ float ws[32][68];
    const int tid = threadIdx.x, ty = tid >> 4, tx = tid & 15;
    const int l0 = blockIdx.x * 64, d0 = blockIdx.y * 64, n = blockIdx.z;
    const float* xn = x + (size_t)n * Cc * Ll;
    u64 acc2[4][4];
    #pragma unroll
    for (int i = 0; i < 4; i++) { acc2[i][0]=0; acc2[i][1]=0; acc2[i][2]=0; acc2[i][3]=0; }
    for (int c0 = 0; c0 < Cc; c0 += 32) {
        for (int i = tid; i < 32*64; i += 128) { int c = i >> 6, l = i & 63; xs[c][l] = xn[(size_t)(c0 + c)*Ll + l0 + l]; }
        for (int i = tid; i < 64*32; i += 128) { int d = i >> 5, c = i & 31; ws[c][d] = g_Win[(d0 + d)*Cc + c0 + c]; }
        __syncthreads();
        #pragma unroll 8
        for (int c = 0; c < 32; c++) {
            ulonglong2 aA = *(const ulonglong2*)&xs[c][ty*8];
            ulonglong2 aB = *(const ulonglong2*)&xs[c][ty*8 + 4];
            float4 b = *(const float4*)&ws[c][tx*4];
            MICRO_FMA2(acc2, aA, aB, b);
        }
        __syncthreads();
    }
    const float b0 = inb[d0+tx*4], b1 = inb[d0+tx*4+1], b2 = inb[d0+tx*4+2], b3 = inb[d0+tx*4+3];
    #pragma unroll
    for (int i2 = 0; i2 < 4; i2++)
        #pragma unroll
        for (int h = 0; h < 2; h++) {
            int l = l0 + ty*8 + i2*2 + h;
            float4 o;
            o.x = (h ? hi32f(acc2[i2][0]) : lo32f(acc2[i2][0])) + b0;
            o.y = (h ? hi32f(acc2[i2][1]) : lo32f(acc2[i2][1])) + b1;
            o.z = (h ? hi32f(acc2[i2][2]) : lo32f(acc2[i2][2])) + b2;
            o.w = (h ? hi32f(acc2[i2][3]) : lo32f(acc2[i2][3])) + b3;
            *(float4*)&g_zet[((size_t)(n*Ll + l))*Dd + d0 + tx*4] = o;
        }
}

// ================= Wq GEMM =================
__global__ void __launch_bounds__(128) wq_gemm_kernel(const float* __restrict__ cb)
{
    __shared__ float as_[32][68];
    __shared__ float bs_[32][68];
    const int tid = threadIdx.x, ty = tid >> 4, tx = tid & 15;
    const int k0 = blockIdx.x * 64, c0 = blockIdx.y * 64;
    u64 acc2[4][4];
    #pragma unroll
    for (int i = 0; i < 4; i++) { acc2[i][0]=0; acc2[i][1]=0; acc2[i][2]=0; acc2[i][3]=0; }
    for (int d0 = 0; d0 < Dd; d0 += 32) {
        for (int i = tid; i < 64*32; i += 128) { int k = i >> 5, d = i & 31; as_[d][k] = cb[(size_t)(k0 + k)*Dd + d0 + d]; }
        for (int i = tid; i < 64*32; i += 128) { int c = i >> 5, d = i & 31; bs_[d][c] = g_Wout[(c0 + c)*Dd + d0 + d]; }
        __syncthreads();
        #pragma unroll 8
        for (int d = 0; d < 32; d++) {
            ulonglong2 aA = *(const ulonglong2*)&as_[d][ty*8];
            ulonglong2 aB = *(const ulonglong2*)&as_[d][ty*8 + 4];
            float4 b = *(const float4*)&bs_[d][tx*4];
            MICRO_FMA2(acc2, aA, aB, b);
        }
        __syncthreads();
    }
    #pragma unroll
    for (int i2 = 0; i2 < 4; i2++)
        #pragma unroll
        for (int h = 0; h < 2; h++) {
            int k = k0 + ty*8 + i2*2 + h;
            float4 o;
            o.x = h ? hi32f(acc2[i2][0]) : lo32f(acc2[i2][0]);
            o.y = h ? hi32f(acc2[i2][1]) : lo32f(acc2[i2][1]);
            o.z = h ? hi32f(acc2[i2][2]) : lo32f(acc2[i2][2]);
            o.w = h ? hi32f(acc2[i2][3]) : lo32f(acc2[i2][3]);
            *(float4*)&g_Wq[(size_t)k*Cc + c0 + tx*4] = o;
        }
}

// ================= anorm + per-launch resets =================
__global__ void __launch_bounds__(256) anorm_kernel()
{
    const int w = threadIdx.x >> 5, lane = threadIdx.x & 31;
    const int pos = blockIdx.x * 8 + w;
    if (blockIdx.x == 0 && threadIdx.x == 0) g_qcnt = 0u;
    const float4* r = (const float4*)(g_zet + (size_t)pos*Dd);
    float4 a = r[lane*2], b = r[lane*2 + 1];
    float s = a.x*a.x + a.y*a.y + a.z*a.z + a.w*a.w + b.x*b.x + b.y*b.y + b.z*b.z + b.w*b.w;
    #pragma unroll
    for (int m = 16; m; m >>= 1) s += __shfl_xor_sync(0xffffffffu, s, m);
    if (lane == 0) { g_anorm[pos] = sqrtf(s); g_sb64[pos] = 0ull; }
}

// ================= fragment-layout bf16 conversions =================
__global__ void __launch_bounds__(256) split_ze_kernel()
{
    const size_t i = (size_t)blockIdx.x * 256 + threadIdx.x;
    const int pos = (int)(i >> 8), d = (int)(i & 255);
    const int r = pos >> 4, row = pos & 15, t = d >> 4, kk = d & 15;
    const int lane = (row & 7)*4 + ((kk & 7) >> 1);
    const int reg = ((kk >> 3) << 1) | (row >> 3);
    const size_t u32i = (((size_t)r*16 + t)*32 + lane)*4 + reg;
    ((__nv_bfloat16*)g_Afr)[u32i*2 + (kk & 1)] = __float2bfloat16(g_zet[i]);
}
__global__ void __launch_bounds__(256) split_cb_kernel(const float* __restrict__ cb)
{
    const size_t i = (size_t)blockIdx.x * 256 + threadIdx.x;
    const int k = (int)(i >> 8), d = (int)(i & 255);
    const int g = k >> 7, rowc = k & 127, j = rowc >> 3, n = rowc & 7;
    const int t = d >> 4, kk = d & 15;
    const int lane = n*4 + ((kk & 7) >> 1);
    const int reg = kk >> 3;
    const size_t u32i = (size_t)g*16384 + (((size_t)t*16 + j)*32 + lane)*2 + reg;
    ((__nv_bfloat16*)g_Bfr)[u32i*2 + (kk & 1)] = __float2bfloat16(cb[i] * g_invn[k]);
}

// ================= single-pass bf16 screen -> global candidate queue =================
// CTA = 128 positions, 256 threads (8 warps: 4 pos-rowgroups x 2 code-colgroups).
// Per tile: slot max -> quad atomicMax to live per-position max (smem) ->
// lanes read the (monotone, possibly stale-lower) max -> any sim >= max-margin
// is PUSHED to a global queue (no dots here). Stale reads only enlarge the
// candidate superset, which always contains the true argmax (R13's bound).
__global__ void __launch_bounds__(256, 1) mma_search_kernel()
{
    extern __shared__ unsigned char dsm[];   // [0,64K): A  [64K,128K): B0  [128K,192K): B1
    __shared__ u32 maxu[128];
    __shared__ float marg[128];

    const int tid = threadIdx.x, w = tid >> 5, lane = tid & 31;
    const int rowgrp = w & 3, colgrp = w >> 2;
    const int p0 = blockIdx.x * 128;
    const uint32_t sbase = smem_u32(dsm);
    const uint4* sAv = (const uint4*)dsm;

    if (tid < 128) {
        maxu[tid] = 0u;
        marg[tid] = 0.012f * g_anorm[p0 + tid];
    }

    // prime: A tile (64KB) + B group 0 (64KB)
    {
        const char* Asrc = (const char*)g_Afr + (size_t)(p0 >> 4) * 8192;
        const char* Bsrc = (const char*)g_Bfr;
        for (int it = 0; it < 16; it++) {
            int off = (it*256 + tid) * 16;
            CPA16(sbase + off, Asrc + off);
            CPA16(sbase + 65536 + off, Bsrc + off);
        }
        CPC();
    }

    int pps[4];
    float mrg[4];
    #pragma unroll
    for (int mt = 0; mt < 2; mt++)
        #pragma unroll
        for (int eh = 0; eh < 2; eh++)
            pps[mt*2 + eh] = rowgrp*32 + mt*16 + (lane >> 2) + eh*8;
    __syncthreads();
    #pragma unroll
    for (int s = 0; s < 4; s++) mrg[s] = marg[pps[s]];

    for (int g = 0; g < 64; g++) {
        __syncthreads();   // prior compute done before overwriting the other buf
        if (g < 63) {
            const char* src = (const char*)g_Bfr + (size_t)(g + 1) * 65536;
            uint32_t dst = sbase + 65536 + ((g + 1) & 1) * 65536;
            for (int it = 0; it < 16; it++) {
                int off = (it*256 + tid) * 16;
                CPA16(dst + off, src + off);
            }
            CPC();
            CPW(1);
        } else {
            CPW(0);
        }
        __syncthreads();

        const uint2* sBv = (const uint2*)(dsm + 65536 + (size_t)(g & 1) * 65536);
        float d0[8][4], d1[8][4];
        #pragma unroll
        for (int t = 0; t < 16; t++) {
            uint4 A0 = sAv[(rowgrp*32 + t)*32 + lane];
            uint4 A1 = sAv[(rowgrp*32 + 16 + t)*32 + lane];
            #pragma unroll
            for (int j = 0; j < 8; j++) {
                uint2 B = sBv[(t*16 + colgrp*8 + j)*32 + lane];
                if (t == 0) { MMA_Z(d0[j], A0, B); MMA_Z(d1[j], A1, B); }
                else        { MMA_AB(d0[j], A0, B); MMA_AB(d1[j], A1, B); }
            }
        }

        // lean epilogue: slot maxima -> live max update -> queue pushes
        float ms[4];
        #pragma unroll
        for (int mt = 0; mt < 2; mt++) {
            float (*dd)[4] = mt ? d1 : d0;
            #pragma unroll
            for (int eh = 0; eh < 2; eh++) {
                const int s = mt*2 + eh;
                float m = fmaxf(dd[0][eh*2], dd[0][eh*2 + 1]);
                #pragma unroll
                for (int j = 1; j < 8; j++)
                    m = fmaxf(m, fmaxf(dd[j][eh*2], dd[j][eh*2 + 1]));
                ms[s] = m;
                float mq = fmaxf(m, __shfl_xor_sync(0xffffffffu, m, 1));
                mq = fmaxf(mq, __shfl_xor_sync(0xffffffffu, mq, 2));
                if ((lane & 3) == 0) atomicMax(&maxu[pps[s]], mono_enc(mq));
            }
        }
        __syncwarp();
        #pragma unroll
        for (int mt = 0; mt < 2; mt++) {
            float (*dd)[4] = mt ? d1 : d0;
            #pragma unroll
            for (int eh = 0; eh < 2; eh++) {
                const int s = mt*2 + eh;
                const float tf = mono_dec(maxu[pps[s]]) - mrg[s];
                if (ms[s] >= tf) {
                    #pragma unroll
                    for (int j = 0; j < 8; j++)
                        #pragma unroll
                        for (int h = 0; h < 2; h++)
                            if (dd[j][eh*2 + h] >= tf) {
                                int k = g*128 + colgrp*64 + j*8 + (lane & 3)*2 + h;
                                u32 qi = atomicAdd(&g_qcnt, 1u);
                                if (qi < QCAP)
                                    g_queue[qi] = ((u32)(p0 + pps[s]) << 13) | (u32)k;
                            }
                }
            }
        }
    }
}

// ================= exact rescore of queued candidates =================
// One warp per entry (looped): warp-cooperative fp32 dot over d=256,
// packed atomicMax -> exact (max value, lowest-k tie) semantics.
__global__ void __launch_bounds__(256) rescore_kernel(const float* __restrict__ cb)
{
    const int nw = gridDim.x * 8;
    const int wg = blockIdx.x * 8 + (threadIdx.x >> 5);
    const int lane = threadIdx.x & 31;
    const u32 cnt = min(g_qcnt, QCAP);
    for (u32 e = wg; e < cnt; e += nw) {
        const u32 ent = g_queue[e];
        const int pos = (int)(ent >> 13), k = (int)(ent & 8191u);
        const float4* ar = (const float4*)(g_zet + (size_t)pos*Dd) + lane*2;
        const float4* br = (const float4*)(cb + (size_t)k*Dd) + lane*2;
        float4 a0 = ar[0], a1 = ar[1], b0 = br[0], b1 = br[1];
        float s = 0.f;
        s = fmaf(a0.x, b0.x, s); s = fmaf(a0.y, b0.y, s);
        s = fmaf(a0.z, b0.z, s); s = fmaf(a0.w, b0.w, s);
        s = fmaf(a1.x, b1.x, s); s = fmaf(a1.y, b1.y, s);
        s = fmaf(a1.z, b1.z, s); s = fmaf(a1.w, b1.w, s);
        #pragma unroll
        for (int m = 16; m; m >>= 1) s += __shfl_xor_sync(0xffffffffu, s, m);
        if (lane == 0) {
            float sim = s * __ldg(&g_invn[k]);
            u64 key = ((u64)mono_enc(sim) << 32) | (u64)(u32)(8191 - k);
            atomicMax(&g_sb64[pos], key);
        }
    }
}

// ================= final index write =================
__global__ void __launch_bounds__(256) write_idx_kernel(float* __restrict__ out)
{
    const int p = blockIdx.x * 256 + threadIdx.x;
    const int k = 8191 - (int)(u32)(g_sb64[p] & 0xFFFFFFFFull);
    g_idx[p] = k;
    out[OUT_Y + p] = (float)k;
}

// ================= VQ loss =================
__global__ void __launch_bounds__(128) loss_kernel(const float* __restrict__ cb)
{
    __shared__ float lred[4];
    const int tid = threadIdx.x;
    const int p0 = blockIdx.x * 64;
    float ls = 0.f;
    for (int i = tid; i < 64*256; i += 128) {
        int pos = i >> 8, d = i & 255;
        int ix = g_idx[p0 + pos];
        float diff = cb[(size_t)ix*Dd + d] - g_zet[(size_t)(p0 + pos)*Dd + d];
        ls = fmaf(diff, diff, ls);
    }
    #pragma unroll
    for (int m = 16; m; m >>= 1) ls += __shfl_xor_sync(0xffffffffu, ls, m);
    if ((tid & 31) == 0) lred[tid >> 5] = ls;
    __syncthreads();
    if (tid == 0) g_losspart[blockIdx.x] = lred[0] + lred[1] + lred[2] + lred[3];
}

// ================= y gather =================
__global__ void __launch_bounds__(256) gather_kernel(
    const float* __restrict__ outb, float* __restrict__ out)
{
    extern __shared__ float sm[];
    __shared__ int sidx[32];
    const int tid = threadIdx.x;
    const int l0 = blockIdx.x * 32, n = blockIdx.y;
    if (tid < 32) sidx[tid] = g_idx[n*Ll + l0 + tid];
    __syncthreads();
    for (int i = tid; i < 32*512; i += 256) {
        int l = i >> 9, c = i & 511;
        sm[l*513 + c] = g_Wq[(size_t)sidx[l]*Cc + c];
    }
    __syncthreads();
    for (int i = tid; i < 512*32; i += 256) {
        int c = i >> 5, l = i & 31;
        out[((size_t)n*Cc + c)*Ll + l0 + l] = sm[l*513 + c] + __ldg(&outb[c]);
    }
}

// ================= finalize losses =================
__global__ void finalize_kernel(float* __restrict__ out)
{
    const int tid = threadIdx.x;
    const int n = tid >> 5, lane = tid & 31;
    float s = g_losspart[n*64 + lane] + g_losspart[n*64 + 32 + lane];
    #pragma unroll
    for (int m = 16; m; m >>= 1) s += __shfl_xor_sync(0xffffffffu, s, m);
    if (lane == 0) {
        float v = s * (1.0f / (float)(Dd * Ll));
        out[OUT_LOSS + n]     = v;
        out[OUT_LOSS + 4 + n] = v;
    }
}

// ================= launch =================
extern "C" void kernel_launch(void* const* d_in, const int* in_sizes, int n_in,
                              void* d_out, int out_size)
{
    (void)in_sizes; (void)n_in; (void)out_size;
    const float* x    = (const float*)d_in[0];
    const float* vin  = (const float*)d_in[1];
    const float* gin  = (const float*)d_in[2];
    const float* bin  = (const float*)d_in[3];
    const float* vout = (const float*)d_in[4];
    const float* gout = (const float*)d_in[5];
    const float* bout = (const float*)d_in[6];
    const float* cb   = (const float*)d_in[7];
    float* out = (float*)d_out;

    const int MMA_SMEM    = 196608;      // 64KB A + 2x64KB B
    const int GATHER_SMEM = 32*513*4;
    cudaFuncSetAttribute(mma_search_kernel, cudaFuncAttributeMaxDynamicSharedMemorySize, MMA_SMEM);
    cudaFuncSetAttribute(mma_search_kernel, cudaFuncAttributePreferredSharedMemoryCarveout, 100);
    cudaFuncSetAttribute(gather_kernel, cudaFuncAttributeMaxDynamicSharedMemorySize, GATHER_SMEM);

    prep_wn_kernel<<<Dd, 128>>>(vin, gin, Cc, 0);
    prep_wn_kernel<<<Cc, 128>>>(vout, gout, Dd, 1);
    prep_cbinv_kernel<<<Kk, 128>>>(cb);
    ze_gemm_kernel<<<dim3(Ll/64, Dd/64, Nn), 128>>>(x, bin);
    anorm_kernel<<<Pp/8, 256>>>();   // also resets g_qcnt / g_sb64
    split_ze_kernel<<<(int)(((size_t)Pp*Dd)/256), 256>>>();
    split_cb_kernel<<<(int)(((size_t)Kk*Dd)/256), 256>>>(cb);
    wq_gemm_kernel<<<dim3(Kk/64, Cc/64), 128>>>(cb);
    mma_search_kernel<<<Pp/128, 256, MMA_SMEM>>>();
    rescore_kernel<<<304, 256>>>(cb);
    write_idx_kernel<<<Pp/256, 256>>>(out);
    loss_kernel<<<Pp/64, 128>>>(cb);
    gather_kernel<<<dim3(Ll/32, Nn), 256, GATHER_SMEM>>>(bout, out);
    finalize_kernel<<<1, 128>>>(out);
}